// round 17
// baseline (speedup 1.0000x reference)
#include <cuda_runtime.h>
#include <cuda_bf16.h>
#include <math.h>
#include <stdint.h>

#define BB     32
#define SS     256
#define ISZ    1024
#define OSZ    1024
#define N4     4096
#define EPSF   1e-5f
#define NBLK   256                 // 2 blocks per SM
#define NTHR   256
#define CHUNK  256
#define NCH    4

// SMEM word-layout (uint32 units). Per block: 16 cols of W.
#define WPITCH 516                 // 512 k-pair words + 4 pad
#define WSPLIT (16 * WPITCH)       // 8256 words per split
#define HBASE  (2 * WSPLIT)        // 16512 words
#define HPITCH 132                 // 128 + 4 pad
#define HSPLIT (32 * HPITCH)       // 4224 words
#define HBUF   (2 * HSPLIT)        // 8448 words (hh + hl, SINGLE buffer)
#define SMEMW  (HBASE + HBUF)      // 24960 words = 99840 B
#define PPITCH 68                  // Pred row pitch (words)

typedef unsigned long long ull;

// Scratch (device globals -- no runtime allocation allowed)
__device__ float         g_xproj[BB * SS * N4];
__device__ __nv_bfloat16 g_xh[BB * SS * ISZ];
__device__ __nv_bfloat16 g_xl[BB * SS * ISZ];
__device__ __nv_bfloat16 g_wh[ISZ * N4];
__device__ __nv_bfloat16 g_wl[ISZ * N4];
__device__ uint32_t      g_hw[BB * OSZ];       // h packed: lo16=hh, hi16=hl
__device__ float         g_part[2][BB][NBLK];
__device__ unsigned      g_bar;

// ---------------------------------------------------------------------------
__device__ __forceinline__ uint32_t pack_h(float h) {
    __nv_bfloat16 hh = __float2bfloat16(h);
    float hf = __bfloat162float(hh);
    __nv_bfloat16 hl = __float2bfloat16(h - hf);
    return (uint32_t)__bfloat16_as_ushort(hh) |
           ((uint32_t)__bfloat16_as_ushort(hl) << 16);
}

__global__ void init_state(const float* __restrict__ init_hx) {
    int j = blockIdx.x * blockDim.x + threadIdx.x;
    if (j == 0) g_bar = 0;
    if (j < BB * OSZ) g_hw[j] = pack_h(init_hx[j & (OSZ - 1)]);
}

__global__ void split_x(const float* __restrict__ x) {
    int i = blockIdx.x * blockDim.x + threadIdx.x;
    float v = x[i];
    __nv_bfloat16 hi = __float2bfloat16(v);
    g_xh[i] = hi;
    g_xl[i] = __float2bfloat16(v - __bfloat162float(hi));
}
__global__ void split_w(const float* __restrict__ W) {
    int i = blockIdx.x * blockDim.x + threadIdx.x;
    float v = W[i];
    __nv_bfloat16 hi = __float2bfloat16(v);
    g_wh[i] = hi;
    g_wl[i] = __float2bfloat16(v - __bfloat162float(hi));
}

// ---------------------------------------------------------------------------
// Tensor-core xproj (proven R14/R16): bf16x3 fused K=3072 GEMM, 128x64 tiles.
// ---------------------------------------------------------------------------
__global__ void __launch_bounds__(256)
xproj_mma(const float* __restrict__ bias) {
    __shared__ uint32_t Aw[128 * 20];
    __shared__ uint32_t Bw[64 * 20];

    const int tid  = threadIdx.x;
    const int lane = tid & 31, wid = tid >> 5;
    const int wm   = wid >> 1;
    const int wn   = wid & 1;
    const int m0   = blockIdx.y * 128;
    const int n0   = blockIdx.x * 64;

    const uint32_t* xh_w = (const uint32_t*)g_xh;
    const uint32_t* xl_w = (const uint32_t*)g_xl;
    const uint32_t* wh_w = (const uint32_t*)g_wh;
    const uint32_t* wl_w = (const uint32_t*)g_wl;

    float d[2][4][4];
    #pragma unroll
    for (int mt = 0; mt < 2; mt++)
        #pragma unroll
        for (int nt = 0; nt < 4; nt++)
            #pragma unroll
            for (int e = 0; e < 4; e++) d[mt][nt][e] = 0.f;

    const int gr = lane >> 2;
    const int gc = lane & 3;

    for (int cc = 0; cc < 96; cc++) {
        const int seg = cc >> 5, kc = cc & 31;
        const uint32_t* As = (seg < 2) ? xh_w : xl_w;
        const uint32_t* Bs = (seg == 1) ? wl_w : wh_w;

        if (cc) __syncthreads();

        #pragma unroll
        for (int u = 0; u < 8; u++) {
            int idx = u * 256 + tid;
            int r = idx >> 4, c = idx & 15;
            Aw[r * 20 + c] = As[(size_t)(m0 + r) * 512 + kc * 16 + c];
        }
        #pragma unroll
        for (int u = 0; u < 4; u++) {
            int idx = u * 256 + tid;
            int k = idx >> 5, nw = idx & 31;
            uint32_t v = Bs[(size_t)(kc * 32 + k) * 2048 + (n0 >> 1) + nw];
            uint16_t* bh = (uint16_t*)Bw;
            bh[(2 * nw)     * 40 + k] = (uint16_t)(v & 0xffffu);
            bh[(2 * nw + 1) * 40 + k] = (uint16_t)(v >> 16);
        }
        __syncthreads();

        #pragma unroll
        for (int ks = 0; ks < 2; ks++) {
            uint32_t a[2][4];
            #pragma unroll
            for (int mt = 0; mt < 2; mt++) {
                int rb = wm * 32 + mt * 16;
                a[mt][0] = Aw[(rb + gr)     * 20 + ks * 8 + gc];
                a[mt][1] = Aw[(rb + 8 + gr) * 20 + ks * 8 + gc];
                a[mt][2] = Aw[(rb + gr)     * 20 + ks * 8 + 4 + gc];
                a[mt][3] = Aw[(rb + 8 + gr) * 20 + ks * 8 + 4 + gc];
            }
            #pragma unroll
            for (int nt = 0; nt < 4; nt++) {
                int nb = wn * 32 + nt * 8;
                uint32_t b0 = Bw[(nb + gr) * 20 + ks * 8 + gc];
                uint32_t b1 = Bw[(nb + gr) * 20 + ks * 8 + 4 + gc];
                #pragma unroll
                for (int mt = 0; mt < 2; mt++) {
                    asm("mma.sync.aligned.m16n8k16.row.col.f32.bf16.bf16.f32 "
                        "{%0,%1,%2,%3}, {%4,%5,%6,%7}, {%8,%9}, {%0,%1,%2,%3};"
                        : "+f"(d[mt][nt][0]), "+f"(d[mt][nt][1]),
                          "+f"(d[mt][nt][2]), "+f"(d[mt][nt][3])
                        : "r"(a[mt][0]), "r"(a[mt][1]), "r"(a[mt][2]), "r"(a[mt][3]),
                          "r"(b0), "r"(b1));
                }
            }
        }
    }

    #pragma unroll
    for (int mt = 0; mt < 2; mt++) {
        #pragma unroll
        for (int nt = 0; nt < 4; nt++) {
            int row = m0 + wm * 32 + mt * 16 + gr;
            int col = n0 + wn * 32 + nt * 8 + gc * 2;
            float2 bv = *(const float2*)(bias + col);
            float2 v0 = { d[mt][nt][0] + bv.x, d[mt][nt][1] + bv.y };
            float2 v1 = { d[mt][nt][2] + bv.x, d[mt][nt][3] + bv.y };
            *(float2*)(g_xproj + (size_t)row * N4 + col)       = v0;
            *(float2*)(g_xproj + (size_t)(row + 8) * N4 + col) = v1;
        }
    }
}

// ---------------------------------------------------------------------------
// Grid barrier -- atomic counter on one hot L2 line (measured best)
// ---------------------------------------------------------------------------
__device__ __forceinline__ void gsync(unsigned target) {
    __syncthreads();
    if (threadIdx.x == 0) {
        __threadfence();
        atomicAdd(&g_bar, 1u);
        while (*(volatile unsigned*)&g_bar < target) { }
        __threadfence();
    }
    __syncthreads();
}

// ---------------------------------------------------------------------------
// Persistent LSTM recurrence -- tensor-core GEMM, 2 BLOCKS PER SM.
// 256 blocks x 16 cols (4 output indices x 4 gates). 8 warps:
// kq = ty&3 (4-way k-split), nh = ty>>2 (two n8 tiles). Single h buffer.
// While one block waits at the grid barrier / LN tail, the co-resident
// block's GEMM+staging fills the SM.
// ---------------------------------------------------------------------------
__global__ void __launch_bounds__(NTHR, 2)
lstm_persist(const float* __restrict__ W,
             const float* __restrict__ gamma,
             const float* __restrict__ beta,
             const float* __restrict__ init_cx,
             float* __restrict__ out) {
    extern __shared__ uint32_t smem[];
    uint32_t* __restrict__ Hst  = smem + HBASE;
    float*    __restrict__ Pred = (float*)(smem + HBASE);    // overlay
    __shared__ float c_sm[BB * 4];

    const int tid = threadIdx.x;
    const int tx  = tid & 31, ty = tid >> 5;
    const int kq  = ty & 3;
    const int nh  = ty >> 2;
    const int blk = blockIdx.x;
    const int txe = tx & 15;                  // valid col lane
    const int gcol = (txe >> 2) * OSZ + blk * 4 + (txe & 3);
    const int b0  = ty * 4;                   // consumer rows (all 8 warps)
    const int gr  = tx >> 2, gc = tx & 3;     // mma fragment coords

    // ---- convert this block's 16 W_h columns to bf16 splits in SMEM ----
    for (int idx = tid; idx < 16 * 512; idx += NTHR) {
        int c = idx & 15, w = idx >> 4;
        int col = (c >> 2) * OSZ + blk * 4 + (c & 3);
        float v0 = W[(size_t)(ISZ + 2 * w)     * N4 + col];
        float v1 = W[(size_t)(ISZ + 2 * w + 1) * N4 + col];
        __nv_bfloat16 h0 = __float2bfloat16(v0);
        __nv_bfloat16 h1 = __float2bfloat16(v1);
        __nv_bfloat16 l0 = __float2bfloat16(v0 - __bfloat162float(h0));
        __nv_bfloat16 l1 = __float2bfloat16(v1 - __bfloat162float(h1));
        smem[0 * WSPLIT + c * WPITCH + w] =
            (uint32_t)__bfloat16_as_ushort(h0) | ((uint32_t)__bfloat16_as_ushort(h1) << 16);
        smem[1 * WSPLIT + c * WPITCH + w] =
            (uint32_t)__bfloat16_as_ushort(l0) | ((uint32_t)__bfloat16_as_ushort(l1) << 16);
    }
    if (tid < BB * 4)
        c_sm[tid] = init_cx[blk * 4 + (tid & 3)];

    const float gam = gamma[gcol];
    const float bet = beta[gcol];

    // staging: 2048 uint4-units per chunk, 8 per thread
    int st_r[8], st_q[8];
    #pragma unroll
    for (int u = 0; u < 8; u++) {
        int j = u * NTHR + tid;
        st_r[u] = j >> 6;
        st_q[u] = j & 63;
    }
    __syncthreads();

    unsigned nsync = 0;

    float px[4];
    #pragma unroll
    for (int r = 0; r < 4; r++)
        px[r] = __ldcg(&g_xproj[((size_t)(b0 + r) * SS + 0) * N4 + gcol]);

    for (int t = 0; t < SS; t++) {
        float cur[4];
        #pragma unroll
        for (int r = 0; r < 4; r++) cur[r] = px[r];
        if (t + 1 < SS) {
            #pragma unroll
            for (int r = 0; r < 4; r++)
                px[r] = __ldcg(&g_xproj[((size_t)(b0 + r) * SS + t + 1) * N4 + gcol]);
        }

        float d[2][2][4];   // [nh-tile is implicit: one nt per warp][mt][elems] -> use [mt][nt=1]: keep [2][2] for symmetry, nt dim=1 used
        #pragma unroll
        for (int mt = 0; mt < 2; mt++)
            #pragma unroll
            for (int e = 0; e < 4; e++) { d[mt][0][e] = 0.f; d[mt][1][e] = 0.f; }

        #pragma unroll 1
        for (int c = 0; c < NCH; c++) {
            __syncthreads();    // buffer free (prev chunk / prev step reads done)
            // ---- stage chunk c ----
            #pragma unroll
            for (int u = 0; u < 8; u++) {
                uint4 ld = __ldcg((const uint4*)(g_hw + (size_t)st_r[u] * OSZ + c * CHUNK + st_q[u] * 4));
                uint32_t hh0 = __byte_perm(ld.x, ld.y, 0x5410);
                uint32_t hl0 = __byte_perm(ld.x, ld.y, 0x7632);
                uint32_t hh1 = __byte_perm(ld.z, ld.w, 0x5410);
                uint32_t hl1 = __byte_perm(ld.z, ld.w, 0x7632);
                int base = st_r[u] * HPITCH + st_q[u] * 2;
                *(uint2*)(Hst + 0 * HSPLIT + base) = make_uint2(hh0, hh1);
                *(uint2*)(Hst + 1 * HSPLIT + base) = make_uint2(hl0, hl1);
            }
            __syncthreads();

            // ---- GEMM chunk c: 3 segments, warp covers k64 (4 ks) ----
            #pragma unroll
            for (int seg = 0; seg < 3; seg++) {
                const uint32_t* __restrict__ As = Hst + ((seg < 2) ? 0 : HSPLIT);
                const uint32_t* __restrict__ Bs = smem + ((seg == 1) ? WSPLIT : 0);
                const int bw0 = c * 128 + kq * 32;

                #pragma unroll
                for (int ks = 0; ks < 4; ks++) {
                    const int aw = kq * 32 + ks * 8;
                    uint32_t a[2][4];
                    #pragma unroll
                    for (int mt = 0; mt < 2; mt++) {
                        int rb = mt * 16;
                        a[mt][0] = As[(rb + gr)     * HPITCH + aw + gc];
                        a[mt][1] = As[(rb + 8 + gr) * HPITCH + aw + gc];
                        a[mt][2] = As[(rb + gr)     * HPITCH + aw + 4 + gc];
                        a[mt][3] = As[(rb + 8 + gr) * HPITCH + aw + 4 + gc];
                    }
                    uint32_t b0 = Bs[(nh * 8 + gr) * WPITCH + bw0 + ks * 8 + gc];
                    uint32_t b1 = Bs[(nh * 8 + gr) * WPITCH + bw0 + ks * 8 + 4 + gc];
                    #pragma unroll
                    for (int mt = 0; mt < 2; mt++) {
                        asm("mma.sync.aligned.m16n8k16.row.col.f32.bf16.bf16.f32 "
                            "{%0,%1,%2,%3}, {%4,%5,%6,%7}, {%8,%9}, {%0,%1,%2,%3};"
                            : "+f"(d[mt][0][0]), "+f"(d[mt][0][1]),
                              "+f"(d[mt][0][2]), "+f"(d[mt][0][3])
                            : "r"(a[mt][0]), "r"(a[mt][1]), "r"(a[mt][2]), "r"(a[mt][3]),
                              "r"(b0), "r"(b1));
                    }
                }
            }
        }
        __syncthreads();    // GEMM reads done before Pred overlay writes

        // ---- write k-partials: Pred[row][kq*16 + col16], pitch 68 ----
        #pragma unroll
        for (int mt = 0; mt < 2; mt++) {
            int row = mt * 16 + gr;
            int col16 = nh * 8 + gc * 2;
            *(float2*)&Pred[row * PPITCH + kq * 16 + col16] =
                make_float2(d[mt][0][0], d[mt][0][1]);
            *(float2*)&Pred[(row + 8) * PPITCH + kq * 16 + col16] =
                make_float2(d[mt][0][2], d[mt][0][3]);
        }
        __syncthreads();

        // ---- consumer: reduce 4 k-partials, LN partials over 16 cols ----
        float acc[4];
        #pragma unroll
        for (int r = 0; r < 4; r++) {
            const int row = b0 + r;
            float sum = 0.f;
            #pragma unroll
            for (int w = 0; w < 4; w++)
                sum += Pred[row * PPITCH + w * 16 + tx];
            acc[r] = sum + cur[r];
        }

        float s[4], ss[4];
        #pragma unroll
        for (int r = 0; r < 4; r++) { s[r] = acc[r]; ss[r] = acc[r] * acc[r]; }
        #pragma unroll
        for (int o = 8; o > 0; o >>= 1) {
            #pragma unroll
            for (int r = 0; r < 4; r++) {
                s[r]  += __shfl_xor_sync(0xffffffffu, s[r],  o);
                ss[r] += __shfl_xor_sync(0xffffffffu, ss[r], o);
            }
        }
        if (tx == 0) {
            #pragma unroll
            for (int r = 0; r < 4; r++) {
                __stcg(&g_part[0][b0 + r][blk], s[r]);
                __stcg(&g_part[1][b0 + r][blk], ss[r]);
            }
        }

        gsync(++nsync * NBLK);

        // ---- aggregate stats: 256 partials per row, 8 per lane ----
        float mean[4], rstd[4];
        #pragma unroll
        for (int r = 0; r < 4; r++) {
            int row = b0 + r;
            float4 sa = __ldcg((const float4*)&g_part[0][row][tx * 8]);
            float4 sb = __ldcg((const float4*)&g_part[0][row][tx * 8 + 4]);
            float4 qa = __ldcg((const float4*)&g_part[1][row][tx * 8]);
            float4 qb = __ldcg((const float4*)&g_part[1][row][tx * 8 + 4]);
            float sl = ((sa.x + sa.y) + (sa.z + sa.w)) + ((sb.x + sb.y) + (sb.z + sb.w));
            float ql = ((qa.x + qa.y) + (qa.z + qa.w)) + ((qb.x + qb.y) + (qb.z + qb.w));
            #pragma unroll
            for (int o = 16; o > 0; o >>= 1) {
                sl += __shfl_xor_sync(0xffffffffu, sl, o);
                ql += __shfl_xor_sync(0xffffffffu, ql, o);
            }
            float m = sl * (1.0f / N4);
            mean[r] = m;
            rstd[r] = rsqrtf(ql * (1.0f / N4) - m * m + EPSF);
        }

        // ---- LN + gates. Gates of index q sit at lanes q, q+4, q+8, q+12 ----
        #pragma unroll
        for (int r = 0; r < 4; r++) {
            float v = (acc[r] - mean[r]) * rstd[r] * gam + bet;
            int qh = tx & 3;
            float a0 = __shfl_sync(0xffffffffu, v, qh);
            float a1 = __shfl_sync(0xffffffffu, v, qh + 4);
            float a2 = __shfl_sync(0xffffffffu, v, qh + 8);
            float a3 = __shfl_sync(0xffffffffu, v, qh + 12);
            if (tx < 4) {
                int b = b0 + r;
                int i = blk * 4 + tx;
                float si = 1.0f / (1.0f + expf(-a0));
                float sf = 1.0f / (1.0f + expf(-a1));
                float so = 1.0f / (1.0f + expf(-a3));
                float co = c_sm[b * 4 + tx];
                float cn = sf * co + si * tanhf(a2);
                float h  = so * cn;
                c_sm[b * 4 + tx] = cn;
                __stcg(&g_hw[(size_t)b * OSZ + i], pack_h(h));
                out[((size_t)b * SS + t) * OSZ + i] = h;
            }
        }

        gsync(++nsync * NBLK);
    }
}

// ---------------------------------------------------------------------------
// Inputs (metadata order): x, W, b, gamma, beta, init_hx, init_cx
// ---------------------------------------------------------------------------
extern "C" void kernel_launch(void* const* d_in, const int* in_sizes, int n_in,
                              void* d_out, int out_size) {
    const float* x       = (const float*)d_in[0];
    const float* W       = (const float*)d_in[1];
    const float* bias    = (const float*)d_in[2];
    const float* gamma   = (const float*)d_in[3];
    const float* beta    = (const float*)d_in[4];
    const float* init_hx = (const float*)d_in[5];
    const float* init_cx = (const float*)d_in[6];
    float* out = (float*)d_out;

    init_state<<<(BB * OSZ + 255) / 256, 256>>>(init_hx);

    split_x<<<(BB * SS * ISZ) / 256, 256>>>(x);
    split_w<<<(ISZ * N4) / 256, 256>>>(W);

    xproj_mma<<<dim3(N4 / 64, (BB * SS) / 128), 256>>>(bias);

    // dynamic smem: SMEMW words = 99840 B per block (2 blocks/SM)
    cudaFuncSetAttribute(lstm_persist,
                         cudaFuncAttributeMaxDynamicSharedMemorySize, SMEMW * 4);
    lstm_persist<<<NBLK, NTHR, SMEMW * 4>>>(W, gamma, beta, init_cx, out);
}